// round 1
// baseline (speedup 1.0000x reference)
#include <cuda_runtime.h>
#include <math.h>

#define S_LEN  2048
#define BATCH  4
#define NHEAD  16
#define DMODEL 1024
#define DHEAD  64
#define MROWS  (BATCH * S_LEN)   // 8192

// ---------------- scratch (no allocations allowed) ----------------
__device__ float g_qp[(size_t)MROWS * DMODEL];
__device__ float g_kp[(size_t)MROWS * DMODEL];
__device__ float g_vp[(size_t)MROWS * DMODEL];
__device__ float g_ao[(size_t)MROWS * DMODEL];

// =================================================================
// C = alpha * A @ B^T (+Res).  A:[M,K] lda, B:[N,K] ldb, row-major.
// Batched over blockIdx.z = b*16+h with separate b/h strides.
// =================================================================
template <int BM, int BN, int BK, int TM, int TN, bool RES>
__global__ __launch_bounds__(256) void gemm_abt(
    const float* __restrict__ A, int lda, long long sAb, long long sAh,
    const float* __restrict__ B, int ldb, long long sBb, long long sBh,
    float* __restrict__ C, int ldc, long long sCb, long long sCh,
    int K, float alpha, const float* __restrict__ Res)
{
    constexpr int TX = BN / TN;
    constexpr int TY = BM / TM;
    constexpr int NT = TX * TY;

    __shared__ float As[BK][BM + 4];
    __shared__ float Bs[BK][BN + 4];

    const int z = blockIdx.z;
    const int b = z >> 4, h = z & 15;
    A += b * sAb + h * sAh;
    B += b * sBb + h * sBh;
    C += b * sCb + h * sCh;

    const int tid = threadIdx.x;
    const int tx = tid % TX, ty = tid / TX;
    const int bm = blockIdx.y * BM, bn = blockIdx.x * BN;

    float acc[TM][TN];
#pragma unroll
    for (int i = 0; i < TM; i++)
#pragma unroll
        for (int j = 0; j < TN; j++) acc[i][j] = 0.0f;

    for (int k0 = 0; k0 < K; k0 += BK) {
#pragma unroll
        for (int i = tid; i < BM * BK / 4; i += NT) {
            int r = i / (BK / 4);
            int c = (i % (BK / 4)) * 4;
            float4 v = *(const float4*)(A + (long long)(bm + r) * lda + k0 + c);
            As[c + 0][r] = v.x; As[c + 1][r] = v.y;
            As[c + 2][r] = v.z; As[c + 3][r] = v.w;
        }
#pragma unroll
        for (int i = tid; i < BN * BK / 4; i += NT) {
            int r = i / (BK / 4);
            int c = (i % (BK / 4)) * 4;
            float4 v = *(const float4*)(B + (long long)(bn + r) * ldb + k0 + c);
            Bs[c + 0][r] = v.x; Bs[c + 1][r] = v.y;
            Bs[c + 2][r] = v.z; Bs[c + 3][r] = v.w;
        }
        __syncthreads();

#pragma unroll
        for (int kk = 0; kk < BK; kk++) {
            float a[TM], bb[TN];
#pragma unroll
            for (int i = 0; i < TM; i++) a[i] = As[kk][ty * TM + i];
#pragma unroll
            for (int j = 0; j < TN; j++) bb[j] = Bs[kk][tx * TN + j];
#pragma unroll
            for (int i = 0; i < TM; i++)
#pragma unroll
                for (int j = 0; j < TN; j++) acc[i][j] = fmaf(a[i], bb[j], acc[i][j]);
        }
        __syncthreads();
    }

#pragma unroll
    for (int i = 0; i < TM; i++) {
        const long long row = (long long)(bm + ty * TM + i);
#pragma unroll
        for (int j = 0; j < TN; j++) {
            const long long col = bn + tx * TN + j;
            float val = alpha * acc[i][j];
            if (RES) val += Res[row * ldc + col];
            C[row * ldc + col] = val;
        }
    }
}

// =================================================================
// C = A @ B.  A:[M,K] lda, B:[K,N] ldb, row-major. Batched like above.
// =================================================================
template <int BM, int BN, int BK, int TM, int TN>
__global__ __launch_bounds__(256) void gemm_ab(
    const float* __restrict__ A, int lda, long long sAb, long long sAh,
    const float* __restrict__ B, int ldb, long long sBb, long long sBh,
    float* __restrict__ C, int ldc, long long sCb, long long sCh,
    int K)
{
    constexpr int TX = BN / TN;
    constexpr int TY = BM / TM;
    constexpr int NT = TX * TY;

    __shared__ float As[BK][BM + 4];
    __shared__ float Bs[BK][BN + 4];

    const int z = blockIdx.z;
    const int b = z >> 4, h = z & 15;
    A += b * sAb + h * sAh;
    B += b * sBb + h * sBh;
    C += b * sCb + h * sCh;

    const int tid = threadIdx.x;
    const int tx = tid % TX, ty = tid / TX;
    const int bm = blockIdx.y * BM, bn = blockIdx.x * BN;

    float acc[TM][TN];
#pragma unroll
    for (int i = 0; i < TM; i++)
#pragma unroll
        for (int j = 0; j < TN; j++) acc[i][j] = 0.0f;

    for (int k0 = 0; k0 < K; k0 += BK) {
#pragma unroll
        for (int i = tid; i < BM * BK / 4; i += NT) {
            int r = i / (BK / 4);
            int c = (i % (BK / 4)) * 4;
            float4 v = *(const float4*)(A + (long long)(bm + r) * lda + k0 + c);
            As[c + 0][r] = v.x; As[c + 1][r] = v.y;
            As[c + 2][r] = v.z; As[c + 3][r] = v.w;
        }
#pragma unroll
        for (int i = tid; i < BK * BN / 4; i += NT) {
            int r = i / (BN / 4);
            int c = (i % (BN / 4)) * 4;
            float4 v = *(const float4*)(B + (long long)(k0 + r) * ldb + bn + c);
            *(float4*)&Bs[r][c] = v;
        }
        __syncthreads();

#pragma unroll
        for (int kk = 0; kk < BK; kk++) {
            float a[TM], bb[TN];
#pragma unroll
            for (int i = 0; i < TM; i++) a[i] = As[kk][ty * TM + i];
#pragma unroll
            for (int j = 0; j < TN; j++) bb[j] = Bs[kk][tx * TN + j];
#pragma unroll
            for (int i = 0; i < TM; i++)
#pragma unroll
                for (int j = 0; j < TN; j++) acc[i][j] = fmaf(a[i], bb[j], acc[i][j]);
        }
        __syncthreads();
    }

#pragma unroll
    for (int i = 0; i < TM; i++) {
        const long long row = (long long)(bm + ty * TM + i);
#pragma unroll
        for (int j = 0; j < TN; j++)
            C[row * ldc + (bn + tx * TN + j)] = acc[i][j];
    }
}

// =================================================================
// In-place row softmax over rows of length S_LEN (2048). 256 threads.
// =================================================================
__global__ __launch_bounds__(256) void softmax_kernel(float* __restrict__ attn)
{
    float* row = attn + (size_t)blockIdx.x * S_LEN;
    const int tid = threadIdx.x;
    __shared__ float sred[8];

    float v[8];
    float m = -1e30f;
#pragma unroll
    for (int j = 0; j < 8; j++) {
        v[j] = row[tid + j * 256];
        m = fmaxf(m, v[j]);
    }
#pragma unroll
    for (int o = 16; o > 0; o >>= 1) m = fmaxf(m, __shfl_xor_sync(0xffffffffu, m, o));
    if ((tid & 31) == 0) sred[tid >> 5] = m;
    __syncthreads();
    m = sred[0];
#pragma unroll
    for (int j = 1; j < 8; j++) m = fmaxf(m, sred[j]);
    __syncthreads();

    float s = 0.0f;
#pragma unroll
    for (int j = 0; j < 8; j++) {
        v[j] = __expf(v[j] - m);
        s += v[j];
    }
#pragma unroll
    for (int o = 16; o > 0; o >>= 1) s += __shfl_xor_sync(0xffffffffu, s, o);
    if ((tid & 31) == 0) sred[tid >> 5] = s;
    __syncthreads();
    s = 0.0f;
#pragma unroll
    for (int j = 0; j < 8; j++) s += sred[j];

    const float inv = 1.0f / s;
#pragma unroll
    for (int j = 0; j < 8; j++) row[tid + j * 256] = v[j] * inv;
}

// =================================================================
// In-place LayerNorm over rows of length DMODEL (1024). 256 threads.
// =================================================================
__global__ __launch_bounds__(256) void ln_kernel(float* __restrict__ x,
                                                 const float* __restrict__ gamma,
                                                 const float* __restrict__ beta)
{
    float* row = x + (size_t)blockIdx.x * DMODEL;
    const int tid = threadIdx.x;
    __shared__ float ssum[8], ssq[8];

    float v[4];
    float s = 0.0f, sq = 0.0f;
#pragma unroll
    for (int j = 0; j < 4; j++) {
        v[j] = row[tid + j * 256];
        s += v[j];
        sq += v[j] * v[j];
    }
#pragma unroll
    for (int o = 16; o > 0; o >>= 1) {
        s  += __shfl_xor_sync(0xffffffffu, s, o);
        sq += __shfl_xor_sync(0xffffffffu, sq, o);
    }
    if ((tid & 31) == 0) { ssum[tid >> 5] = s; ssq[tid >> 5] = sq; }
    __syncthreads();
    s = 0.0f; sq = 0.0f;
#pragma unroll
    for (int j = 0; j < 8; j++) { s += ssum[j]; sq += ssq[j]; }

    const float mu = s * (1.0f / DMODEL);
    const float var = sq * (1.0f / DMODEL) - mu * mu;
    const float rstd = rsqrtf(var + 1e-6f);
#pragma unroll
    for (int j = 0; j < 4; j++) {
        const int c = tid + j * 256;
        row[c] = (v[j] - mu) * rstd * gamma[c] + beta[c];
    }
}

// =================================================================
extern "C" void kernel_launch(void* const* d_in, const int* in_sizes, int n_in,
                              void* d_out, int out_size)
{
    const float* q     = (const float*)d_in[0];
    const float* k     = (const float*)d_in[1];
    const float* v     = (const float*)d_in[2];
    const float* w_q   = (const float*)d_in[3];
    const float* w_k   = (const float*)d_in[4];
    const float* w_v   = (const float*)d_in[5];
    const float* w_fc  = (const float*)d_in[6];
    const float* gamma = (const float*)d_in[7];
    const float* beta  = (const float*)d_in[8];

    float *qp, *kp, *vp, *ao;
    cudaGetSymbolAddress((void**)&qp, g_qp);
    cudaGetSymbolAddress((void**)&kp, g_kp);
    cudaGetSymbolAddress((void**)&vp, g_vp);
    cudaGetSymbolAddress((void**)&ao, g_ao);

    float* out  = (float*)d_out;
    float* attn = out + (size_t)MROWS * DMODEL;   // [B, H, Sq, Sk] fp32

    dim3 blk(256);

    // --- projections: X[8192,1024] @ W^T[1024,1024] ---
    {
        dim3 g(DMODEL / 128, MROWS / 128, 1);
        gemm_abt<128, 128, 16, 8, 8, false><<<g, blk>>>(
            q, DMODEL, 0, 0, w_q, DMODEL, 0, 0, qp, DMODEL, 0, 0,
            DMODEL, 1.0f, nullptr);
        gemm_abt<128, 128, 16, 8, 8, false><<<g, blk>>>(
            k, DMODEL, 0, 0, w_k, DMODEL, 0, 0, kp, DMODEL, 0, 0,
            DMODEL, 1.0f, nullptr);
        gemm_abt<128, 128, 16, 8, 8, false><<<g, blk>>>(
            v, DMODEL, 0, 0, w_v, DMODEL, 0, 0, vp, DMODEL, 0, 0,
            DMODEL, 1.0f, nullptr);
    }

    // --- scores: per (b,h) Qh[2048,64] @ Kh^T -> attn logits ---
    {
        dim3 g(S_LEN / 128, S_LEN / 128, BATCH * NHEAD);
        gemm_abt<128, 128, 16, 8, 8, false><<<g, blk>>>(
            qp, DMODEL, (long long)S_LEN * DMODEL, DHEAD,
            kp, DMODEL, (long long)S_LEN * DMODEL, DHEAD,
            attn, S_LEN, (long long)NHEAD * S_LEN * S_LEN, (long long)S_LEN * S_LEN,
            DHEAD, 0.125f, nullptr);
    }

    // --- softmax in place over attn rows ---
    softmax_kernel<<<BATCH * NHEAD * S_LEN, blk>>>(attn);

    // --- PV: per (b,h) attn[2048,2048] @ Vh[2048,64] ---
    {
        dim3 g(DHEAD / 64, S_LEN / 128, BATCH * NHEAD);
        gemm_ab<128, 64, 16, 8, 4><<<g, blk>>>(
            attn, S_LEN, (long long)NHEAD * S_LEN * S_LEN, (long long)S_LEN * S_LEN,
            vp, DMODEL, (long long)S_LEN * DMODEL, DHEAD,
            ao, DMODEL, (long long)S_LEN * DMODEL, DHEAD,
            S_LEN);
    }

    // --- fc + residual ---
    {
        dim3 g(DMODEL / 128, MROWS / 128, 1);
        gemm_abt<128, 128, 16, 8, 8, true><<<g, blk>>>(
            ao, DMODEL, 0, 0, w_fc, DMODEL, 0, 0, out, DMODEL, 0, 0,
            DMODEL, 1.0f, q);
    }

    // --- layernorm in place ---
    ln_kernel<<<MROWS, blk>>>(out, gamma, beta);
}

// round 3
// speedup vs baseline: 1.7663x; 1.7663x over previous
#include <cuda_runtime.h>
#include <math.h>
#include <stdint.h>

#define S_LEN  2048
#define BATCH  4
#define NHEAD  16
#define DMODEL 1024
#define DHEAD  64
#define MROWS  (BATCH * S_LEN)   // 8192

// ---------------- scratch (no allocations allowed) ----------------
__device__ float g_qp[(size_t)MROWS * DMODEL];
__device__ float g_kp[(size_t)MROWS * DMODEL];
__device__ float g_vp[(size_t)MROWS * DMODEL];
__device__ float g_ao[(size_t)MROWS * DMODEL];

// ---------------- helpers ----------------
__device__ __forceinline__ void mma_tf32(float c[4], const uint32_t a[4], const uint32_t b[2]) {
    asm volatile(
        "mma.sync.aligned.m16n8k8.row.col.f32.tf32.tf32.f32 "
        "{%0,%1,%2,%3}, {%4,%5,%6,%7}, {%8,%9}, {%0,%1,%2,%3};\n"
        : "+f"(c[0]), "+f"(c[1]), "+f"(c[2]), "+f"(c[3])
        : "r"(a[0]), "r"(a[1]), "r"(a[2]), "r"(a[3]), "r"(b[0]), "r"(b[1]));
}

__device__ __forceinline__ uint32_t f2tf32(float x) {
    uint32_t r;
    asm("cvt.rna.tf32.f32 %0, %1;\n" : "=r"(r) : "f"(x));
    return r;
}

__device__ __forceinline__ void cp_async16(uint32_t smem_addr, const void* gptr) {
    asm volatile("cp.async.cg.shared.global [%0], [%1], 16;\n" :: "r"(smem_addr), "l"(gptr));
}
__device__ __forceinline__ void cp_commit() { asm volatile("cp.async.commit_group;\n"); }
template <int N> __device__ __forceinline__ void cp_wait() {
    asm volatile("cp.async.wait_group %0;\n" :: "n"(N));
}

// =================================================================
// Tensor-core tf32 GEMM.
//   TRANSB=1: C = alpha*A@B^T (+Res). A:[M,K] lda, B:[N,K] ldb.
//   TRANSB=0: C = alpha*A@B   (+Res). A:[M,K] lda, B:[K,N] ldb.
//   TRIPLE=1: 3xTF32 error compensation (near-fp32 accuracy).
// Row-major everywhere. Batched over blockIdx.z = b*16+h.
// 256 threads = 8 warps. BK=32.
// =================================================================
template <int BM, int BN, int BK, int WM, int WN, bool TRANSB, bool RES, bool TRIPLE>
__global__ __launch_bounds__(256) void gemm_tc(
    const float* __restrict__ A, int lda, long long sAb, long long sAh,
    const float* __restrict__ B, int ldb, long long sBb, long long sBh,
    float* __restrict__ C, int ldc, long long sCb, long long sCh,
    int K, float alpha, const float* __restrict__ Res)
{
    constexpr int MI = WM / 16;
    constexpr int NI = WN / 8;
    constexpr int WARPS_N = BN / WN;
    constexpr int A_WORDS = BM * (BK + 4);
    constexpr int B_WORDS = TRANSB ? BN * (BK + 4) : BK * (BN + 4);
    constexpr int STAGE_WORDS = A_WORDS + B_WORDS;

    extern __shared__ float smemf[];

    const int z = blockIdx.z;
    const int b = z >> 4, h = z & 15;
    A += b * sAb + h * sAh;
    B += b * sBb + h * sBh;
    C += b * sCb + h * sCh;

    const int tid  = threadIdx.x;
    const int warp = tid >> 5;
    const int lane = tid & 31;
    const int g = lane >> 2;
    const int t = lane & 3;
    const int wm0 = (warp / WARPS_N) * WM;
    const int wn0 = (warp % WARPS_N) * WN;
    const int bm = blockIdx.y * BM, bn = blockIdx.x * BN;

    float acc[MI][NI][4];
#pragma unroll
    for (int i = 0; i < MI; i++)
#pragma unroll
        for (int j = 0; j < NI; j++)
#pragma unroll
            for (int r = 0; r < 4; r++) acc[i][j][r] = 0.0f;

    const int nIter = K / BK;

    auto load_tile = [&](int it, int stage) {
        float* As = smemf + stage * STAGE_WORDS;
        float* Bs = As + A_WORDS;
        const int k0 = it * BK;
#pragma unroll
        for (int i = tid; i < BM * BK / 4; i += 256) {
            int r = i / (BK / 4);
            int c = (i % (BK / 4)) * 4;
            uint32_t dst = (uint32_t)__cvta_generic_to_shared(As + r * (BK + 4) + c);
            cp_async16(dst, A + (long long)(bm + r) * lda + k0 + c);
        }
        if (TRANSB) {
#pragma unroll
            for (int i = tid; i < BN * BK / 4; i += 256) {
                int r = i / (BK / 4);
                int c = (i % (BK / 4)) * 4;
                uint32_t dst = (uint32_t)__cvta_generic_to_shared(Bs + r * (BK + 4) + c);
                cp_async16(dst, B + (long long)(bn + r) * ldb + k0 + c);
            }
        } else {
#pragma unroll
            for (int i = tid; i < BK * BN / 4; i += 256) {
                int r = i / (BN / 4);
                int c = (i % (BN / 4)) * 4;
                uint32_t dst = (uint32_t)__cvta_generic_to_shared(Bs + r * (BN + 4) + c);
                cp_async16(dst, B + (long long)(k0 + r) * ldb + bn + c);
            }
        }
    };

    load_tile(0, 0);
    cp_commit();

    for (int it = 0; it < nIter; it++) {
        if (it + 1 < nIter) {
            load_tile(it + 1, (it + 1) & 1);
            cp_commit();
            cp_wait<1>();
        } else {
            cp_wait<0>();
        }
        __syncthreads();

        const float* As = smemf + (it & 1) * STAGE_WORDS;
        const float* Bs = As + A_WORDS;

#pragma unroll
        for (int ks = 0; ks < BK / 8; ks++) {
            float afv[MI][4];
#pragma unroll
            for (int mi = 0; mi < MI; mi++) {
                const int r0 = wm0 + mi * 16 + g;
                const int c0 = ks * 8 + t;
                afv[mi][0] = As[(r0    ) * (BK + 4) + c0    ];
                afv[mi][1] = As[(r0 + 8) * (BK + 4) + c0    ];
                afv[mi][2] = As[(r0    ) * (BK + 4) + c0 + 4];
                afv[mi][3] = As[(r0 + 8) * (BK + 4) + c0 + 4];
            }
            float bfv[NI][2];
#pragma unroll
            for (int ni = 0; ni < NI; ni++) {
                if (TRANSB) {
                    const int n0 = wn0 + ni * 8 + g;
                    bfv[ni][0] = Bs[n0 * (BK + 4) + ks * 8 + t    ];
                    bfv[ni][1] = Bs[n0 * (BK + 4) + ks * 8 + t + 4];
                } else {
                    const int n0 = wn0 + ni * 8 + g;
                    bfv[ni][0] = Bs[(ks * 8 + t    ) * (BN + 4) + n0];
                    bfv[ni][1] = Bs[(ks * 8 + t + 4) * (BN + 4) + n0];
                }
            }

            if (TRIPLE) {
                uint32_t ah[MI][4], al[MI][4], bh[NI][2], bl[NI][2];
#pragma unroll
                for (int mi = 0; mi < MI; mi++)
#pragma unroll
                    for (int r = 0; r < 4; r++) {
                        ah[mi][r] = f2tf32(afv[mi][r]);
                        al[mi][r] = f2tf32(afv[mi][r] - __uint_as_float(ah[mi][r]));
                    }
#pragma unroll
                for (int ni = 0; ni < NI; ni++)
#pragma unroll
                    for (int r = 0; r < 2; r++) {
                        bh[ni][r] = f2tf32(bfv[ni][r]);
                        bl[ni][r] = f2tf32(bfv[ni][r] - __uint_as_float(bh[ni][r]));
                    }
#pragma unroll
                for (int mi = 0; mi < MI; mi++)
#pragma unroll
                    for (int ni = 0; ni < NI; ni++) {
                        mma_tf32(acc[mi][ni], al[mi], bh[ni]);
                        mma_tf32(acc[mi][ni], ah[mi], bl[ni]);
                        mma_tf32(acc[mi][ni], ah[mi], bh[ni]);
                    }
            } else {
                uint32_t ah[MI][4], bh[NI][2];
#pragma unroll
                for (int mi = 0; mi < MI; mi++)
#pragma unroll
                    for (int r = 0; r < 4; r++) ah[mi][r] = f2tf32(afv[mi][r]);
#pragma unroll
                for (int ni = 0; ni < NI; ni++)
#pragma unroll
                    for (int r = 0; r < 2; r++) bh[ni][r] = f2tf32(bfv[ni][r]);
#pragma unroll
                for (int mi = 0; mi < MI; mi++)
#pragma unroll
                    for (int ni = 0; ni < NI; ni++)
                        mma_tf32(acc[mi][ni], ah[mi], bh[ni]);
            }
        }
        __syncthreads();
    }

    // ---- epilogue ----
#pragma unroll
    for (int mi = 0; mi < MI; mi++) {
#pragma unroll
        for (int ni = 0; ni < NI; ni++) {
            const long long row0 = bm + wm0 + mi * 16 + g;
            const long long col0 = bn + wn0 + ni * 8 + t * 2;
            float2 v0, v1;
            v0.x = alpha * acc[mi][ni][0];
            v0.y = alpha * acc[mi][ni][1];
            v1.x = alpha * acc[mi][ni][2];
            v1.y = alpha * acc[mi][ni][3];
            if (RES) {
                const float2 r0 = *(const float2*)(Res + row0 * ldc + col0);
                const float2 r1 = *(const float2*)(Res + (row0 + 8) * ldc + col0);
                v0.x += r0.x; v0.y += r0.y;
                v1.x += r1.x; v1.y += r1.y;
            }
            *(float2*)(C + row0 * ldc + col0) = v0;
            *(float2*)(C + (row0 + 8) * ldc + col0) = v1;
        }
    }
}

// =================================================================
// In-place row softmax over rows of length S_LEN (2048). 256 threads.
// =================================================================
__global__ __launch_bounds__(256) void softmax_kernel(float* __restrict__ attn)
{
    float* row = attn + (size_t)blockIdx.x * S_LEN;
    const int tid = threadIdx.x;
    __shared__ float sred[8];

    float v[8];
    float m = -1e30f;
#pragma unroll
    for (int j = 0; j < 8; j++) {
        v[j] = row[tid + j * 256];
        m = fmaxf(m, v[j]);
    }
#pragma unroll
    for (int o = 16; o > 0; o >>= 1) m = fmaxf(m, __shfl_xor_sync(0xffffffffu, m, o));
    if ((tid & 31) == 0) sred[tid >> 5] = m;
    __syncthreads();
    m = sred[0];
#pragma unroll
    for (int j = 1; j < 8; j++) m = fmaxf(m, sred[j]);
    __syncthreads();

    float s = 0.0f;
#pragma unroll
    for (int j = 0; j < 8; j++) {
        v[j] = __expf(v[j] - m);
        s += v[j];
    }
#pragma unroll
    for (int o = 16; o > 0; o >>= 1) s += __shfl_xor_sync(0xffffffffu, s, o);
    if ((tid & 31) == 0) sred[tid >> 5] = s;
    __syncthreads();
    s = 0.0f;
#pragma unroll
    for (int j = 0; j < 8; j++) s += sred[j];

    const float inv = 1.0f / s;
#pragma unroll
    for (int j = 0; j < 8; j++) row[tid + j * 256] = v[j] * inv;
}

// =================================================================
// In-place LayerNorm over rows of length DMODEL (1024). 256 threads.
// =================================================================
__global__ __launch_bounds__(256) void ln_kernel(float* __restrict__ x,
                                                 const float* __restrict__ gamma,
                                                 const float* __restrict__ beta)
{
    float* row = x + (size_t)blockIdx.x * DMODEL;
    const int tid = threadIdx.x;
    __shared__ float ssum[8], ssq[8];

    float v[4];
    float s = 0.0f, sq = 0.0f;
#pragma unroll
    for (int j = 0; j < 4; j++) {
        v[j] = row[tid + j * 256];
        s += v[j];
        sq += v[j] * v[j];
    }
#pragma unroll
    for (int o = 16; o > 0; o >>= 1) {
        s  += __shfl_xor_sync(0xffffffffu, s, o);
        sq += __shfl_xor_sync(0xffffffffu, sq, o);
    }
    if ((tid & 31) == 0) { ssum[tid >> 5] = s; ssq[tid >> 5] = sq; }
    __syncthreads();
    s = 0.0f; sq = 0.0f;
#pragma unroll
    for (int j = 0; j < 8; j++) { s += ssum[j]; sq += ssq[j]; }

    const float mu = s * (1.0f / DMODEL);
    const float var = sq * (1.0f / DMODEL) - mu * mu;
    const float rstd = rsqrtf(var + 1e-6f);
#pragma unroll
    for (int j = 0; j < 4; j++) {
        const int c = tid + j * 256;
        row[c] = (v[j] - mu) * rstd * gamma[c] + beta[c];
    }
}

// =================================================================
static constexpr int ABT_SMEM = 2 * (128 * 36 + 128 * 36) * 4;      // 73728 B
static constexpr int AB_SMEM  = 2 * (128 * 36 + 32 * 68) * 4;       // 54272 B

extern "C" void kernel_launch(void* const* d_in, const int* in_sizes, int n_in,
                              void* d_out, int out_size)
{
    const float* q     = (const float*)d_in[0];
    const float* k     = (const float*)d_in[1];
    const float* v     = (const float*)d_in[2];
    const float* w_q   = (const float*)d_in[3];
    const float* w_k   = (const float*)d_in[4];
    const float* w_v   = (const float*)d_in[5];
    const float* w_fc  = (const float*)d_in[6];
    const float* gamma = (const float*)d_in[7];
    const float* beta  = (const float*)d_in[8];

    float *qp, *kp, *vp, *ao;
    cudaGetSymbolAddress((void**)&qp, g_qp);
    cudaGetSymbolAddress((void**)&kp, g_kp);
    cudaGetSymbolAddress((void**)&vp, g_vp);
    cudaGetSymbolAddress((void**)&ao, g_ao);

    float* out  = (float*)d_out;
    float* attn = out + (size_t)MROWS * DMODEL;   // [B, H, Sq, Sk] fp32

    cudaFuncSetAttribute(gemm_tc<128,128,32,32,64,true,false,true>,
                         cudaFuncAttributeMaxDynamicSharedMemorySize, ABT_SMEM);
    cudaFuncSetAttribute(gemm_tc<128,128,32,32,64,true,false,false>,
                         cudaFuncAttributeMaxDynamicSharedMemorySize, ABT_SMEM);
    cudaFuncSetAttribute(gemm_tc<128,128,32,32,64,true,true,false>,
                         cudaFuncAttributeMaxDynamicSharedMemorySize, ABT_SMEM);
    cudaFuncSetAttribute(gemm_tc<128,64,32,32,32,false,false,false>,
                         cudaFuncAttributeMaxDynamicSharedMemorySize, AB_SMEM);

    dim3 blk(256);

    // --- projections: X[8192,1024] @ W^T[1024,1024] ---
    {
        dim3 g(DMODEL / 128, MROWS / 128, 1);
        // Q and K feed the softmax — 3xTF32 for near-fp32 accuracy
        gemm_tc<128,128,32,32,64,true,false,true><<<g, blk, ABT_SMEM>>>(
            q, DMODEL, 0, 0, w_q, DMODEL, 0, 0, qp, DMODEL, 0, 0,
            DMODEL, 1.0f, nullptr);
        gemm_tc<128,128,32,32,64,true,false,true><<<g, blk, ABT_SMEM>>>(
            k, DMODEL, 0, 0, w_k, DMODEL, 0, 0, kp, DMODEL, 0, 0,
            DMODEL, 1.0f, nullptr);
        // V only feeds output 0 (passed at 1.8e-4 with single tf32)
        gemm_tc<128,128,32,32,64,true,false,false><<<g, blk, ABT_SMEM>>>(
            v, DMODEL, 0, 0, w_v, DMODEL, 0, 0, vp, DMODEL, 0, 0,
            DMODEL, 1.0f, nullptr);
    }

    // --- scores: per (b,h) Qh[2048,64] @ Kh^T * 0.125 (3xTF32) ---
    {
        dim3 g(S_LEN / 128, S_LEN / 128, BATCH * NHEAD);
        gemm_tc<128,128,32,32,64,true,false,true><<<g, blk, ABT_SMEM>>>(
            qp, DMODEL, (long long)S_LEN * DMODEL, DHEAD,
            kp, DMODEL, (long long)S_LEN * DMODEL, DHEAD,
            attn, S_LEN, (long long)NHEAD * S_LEN * S_LEN, (long long)S_LEN * S_LEN,
            DHEAD, 0.125f, nullptr);
    }

    // --- softmax in place over attn rows ---
    softmax_kernel<<<BATCH * NHEAD * S_LEN, blk>>>(attn);

    // --- PV: per (b,h) attn[2048,2048] @ Vh[2048,64] ---
    {
        dim3 g(DHEAD / 64, S_LEN / 128, BATCH * NHEAD);
        gemm_tc<128,64,32,32,32,false,false,false><<<g, blk, AB_SMEM>>>(
            attn, S_LEN, (long long)NHEAD * S_LEN * S_LEN, (long long)S_LEN * S_LEN,
            vp, DMODEL, (long long)S_LEN * DMODEL, DHEAD,
            ao, DMODEL, (long long)S_LEN * DMODEL, DHEAD,
            S_LEN, 1.0f, nullptr);
    }

    // --- fc + residual ---
    {
        dim3 g(DMODEL / 128, MROWS / 128, 1);
        gemm_tc<128,128,32,32,64,true,true,false><<<g, blk, ABT_SMEM>>>(
            ao, DMODEL, 0, 0, w_fc, DMODEL, 0, 0, out, DMODEL, 0, 0,
            DMODEL, 1.0f, q);
    }

    // --- layernorm in place ---
    ln_kernel<<<MROWS, blk>>>(out, gamma, beta);
}

// round 4
// speedup vs baseline: 1.9998x; 1.1322x over previous
#include <cuda_runtime.h>
#include <math.h>
#include <stdint.h>

#define S_LEN  2048
#define BATCH  4
#define NHEAD  16
#define DMODEL 1024
#define DHEAD  64
#define MROWS  (BATCH * S_LEN)   // 8192
#define NZ     (BATCH * NHEAD)   // 64
#define NCHUNK 32                // S_LEN / 64 column chunks in scores grid.x

// ---------------- scratch (no allocations allowed) ----------------
__device__ float g_qp[(size_t)MROWS * DMODEL];
__device__ float g_kp[(size_t)MROWS * DMODEL];
__device__ float g_vp[(size_t)MROWS * DMODEL];
__device__ float g_ao[(size_t)MROWS * DMODEL];
__device__ float g_part[(size_t)NZ * S_LEN * NCHUNK];   // per-row partial exp sums

// ---------------- helpers ----------------
__device__ __forceinline__ void mma_tf32(float c[4], const uint32_t a[4], const uint32_t b[2]) {
    asm volatile(
        "mma.sync.aligned.m16n8k8.row.col.f32.tf32.tf32.f32 "
        "{%0,%1,%2,%3}, {%4,%5,%6,%7}, {%8,%9}, {%0,%1,%2,%3};\n"
        : "+f"(c[0]), "+f"(c[1]), "+f"(c[2]), "+f"(c[3])
        : "r"(a[0]), "r"(a[1]), "r"(a[2]), "r"(a[3]), "r"(b[0]), "r"(b[1]));
}
__device__ __forceinline__ uint32_t f2tf32(float x) {
    uint32_t r;
    asm("cvt.rna.tf32.f32 %0, %1;\n" : "=r"(r) : "f"(x));
    return r;
}
__device__ __forceinline__ void cp_async16(uint32_t smem_addr, const void* gptr) {
    asm volatile("cp.async.cg.shared.global [%0], [%1], 16;\n" :: "r"(smem_addr), "l"(gptr));
}
__device__ __forceinline__ void cp_commit() { asm volatile("cp.async.commit_group;\n"); }
template <int N> __device__ __forceinline__ void cp_wait() {
    asm volatile("cp.async.wait_group %0;\n" :: "n"(N));
}

// =================================================================
// Generic tensor-core tf32 GEMM (projections / fc).
// =================================================================
template <int BM, int BN, int BK, int WM, int WN, bool TRANSB, bool RES, bool TRIPLE, int LBB>
__global__ __launch_bounds__(256, LBB) void gemm_tc(
    const float* __restrict__ A, int lda,
    const float* __restrict__ B, int ldb,
    float* __restrict__ C, int ldc,
    int K, float alpha, const float* __restrict__ Res)
{
    constexpr int MI = WM / 16;
    constexpr int NI = WN / 8;
    constexpr int WARPS_N = BN / WN;
    constexpr int A_WORDS = BM * (BK + 4);
    constexpr int B_WORDS = TRANSB ? BN * (BK + 4) : BK * (BN + 4);
    constexpr int STAGE_WORDS = A_WORDS + B_WORDS;

    extern __shared__ float smemf[];

    const int tid  = threadIdx.x;
    const int warp = tid >> 5;
    const int lane = tid & 31;
    const int g = lane >> 2;
    const int t = lane & 3;
    const int wm0 = (warp / WARPS_N) * WM;
    const int wn0 = (warp % WARPS_N) * WN;
    const int bm = blockIdx.y * BM, bn = blockIdx.x * BN;

    float acc[MI][NI][4];
#pragma unroll
    for (int i = 0; i < MI; i++)
#pragma unroll
        for (int j = 0; j < NI; j++)
#pragma unroll
            for (int r = 0; r < 4; r++) acc[i][j][r] = 0.0f;

    const int nIter = K / BK;

    auto load_tile = [&](int it, int stage) {
        float* As = smemf + stage * STAGE_WORDS;
        float* Bs = As + A_WORDS;
        const int k0 = it * BK;
#pragma unroll
        for (int i = tid; i < BM * BK / 4; i += 256) {
            int r = i / (BK / 4);
            int c = (i % (BK / 4)) * 4;
            uint32_t dst = (uint32_t)__cvta_generic_to_shared(As + r * (BK + 4) + c);
            cp_async16(dst, A + (long long)(bm + r) * lda + k0 + c);
        }
        if (TRANSB) {
#pragma unroll
            for (int i = tid; i < BN * BK / 4; i += 256) {
                int r = i / (BK / 4);
                int c = (i % (BK / 4)) * 4;
                uint32_t dst = (uint32_t)__cvta_generic_to_shared(Bs + r * (BK + 4) + c);
                cp_async16(dst, B + (long long)(bn + r) * ldb + k0 + c);
            }
        } else {
#pragma unroll
            for (int i = tid; i < BK * BN / 4; i += 256) {
                int r = i / (BN / 4);
                int c = (i % (BN / 4)) * 4;
                uint32_t dst = (uint32_t)__cvta_generic_to_shared(Bs + r * (BN + 4) + c);
                cp_async16(dst, B + (long long)(k0 + r) * ldb + bn + c);
            }
        }
    };

    load_tile(0, 0);
    cp_commit();

    for (int it = 0; it < nIter; it++) {
        if (it + 1 < nIter) {
            load_tile(it + 1, (it + 1) & 1);
            cp_commit();
            cp_wait<1>();
        } else {
            cp_wait<0>();
        }
        __syncthreads();

        const float* As = smemf + (it & 1) * STAGE_WORDS;
        const float* Bs = As + A_WORDS;

#pragma unroll
        for (int ks = 0; ks < BK / 8; ks++) {
            float afv[MI][4];
#pragma unroll
            for (int mi = 0; mi < MI; mi++) {
                const int r0 = wm0 + mi * 16 + g;
                const int c0 = ks * 8 + t;
                afv[mi][0] = As[(r0    ) * (BK + 4) + c0    ];
                afv[mi][1] = As[(r0 + 8) * (BK + 4) + c0    ];
                afv[mi][2] = As[(r0    ) * (BK + 4) + c0 + 4];
                afv[mi][3] = As[(r0 + 8) * (BK + 4) + c0 + 4];
            }
            float bfv[NI][2];
#pragma unroll
            for (int ni = 0; ni < NI; ni++) {
                if (TRANSB) {
                    const int n0 = wn0 + ni * 8 + g;
                    bfv[ni][0] = Bs[n0 * (BK + 4) + ks * 8 + t    ];
                    bfv[ni][1] = Bs[n0 * (BK + 4) + ks * 8 + t + 4];
                } else {
                    const int n0 = wn0 + ni * 8 + g;
                    bfv[ni][0] = Bs[(ks * 8 + t    ) * (BN + 4) + n0];
                    bfv[ni][1] = Bs[(ks * 8 + t + 4) * (BN + 4) + n0];
                }
            }
            if (TRIPLE) {
                uint32_t ah[MI][4], al[MI][4], bh[NI][2], bl[NI][2];
#pragma unroll
                for (int mi = 0; mi < MI; mi++)
#pragma unroll
                    for (int r = 0; r < 4; r++) {
                        ah[mi][r] = f2tf32(afv[mi][r]);
                        al[mi][r] = f2tf32(afv[mi][r] - __uint_as_float(ah[mi][r]));
                    }
#pragma unroll
                for (int ni = 0; ni < NI; ni++)
#pragma unroll
                    for (int r = 0; r < 2; r++) {
                        bh[ni][r] = f2tf32(bfv[ni][r]);
                        bl[ni][r] = f2tf32(bfv[ni][r] - __uint_as_float(bh[ni][r]));
                    }
#pragma unroll
                for (int mi = 0; mi < MI; mi++)
#pragma unroll
                    for (int ni = 0; ni < NI; ni++) {
                        mma_tf32(acc[mi][ni], al[mi], bh[ni]);
                        mma_tf32(acc[mi][ni], ah[mi], bl[ni]);
                        mma_tf32(acc[mi][ni], ah[mi], bh[ni]);
                    }
            } else {
                uint32_t ah[MI][4], bh[NI][2];
#pragma unroll
                for (int mi = 0; mi < MI; mi++)
#pragma unroll
                    for (int r = 0; r < 4; r++) ah[mi][r] = f2tf32(afv[mi][r]);
#pragma unroll
                for (int ni = 0; ni < NI; ni++)
#pragma unroll
                    for (int r = 0; r < 2; r++) bh[ni][r] = f2tf32(bfv[ni][r]);
#pragma unroll
                for (int mi = 0; mi < MI; mi++)
#pragma unroll
                    for (int ni = 0; ni < NI; ni++)
                        mma_tf32(acc[mi][ni], ah[mi], bh[ni]);
            }
        }
        __syncthreads();
    }

#pragma unroll
    for (int mi = 0; mi < MI; mi++) {
#pragma unroll
        for (int ni = 0; ni < NI; ni++) {
            const long long row0 = bm + wm0 + mi * 16 + g;
            const long long col0 = bn + wn0 + ni * 8 + t * 2;
            float2 v0, v1;
            v0.x = alpha * acc[mi][ni][0];
            v0.y = alpha * acc[mi][ni][1];
            v1.x = alpha * acc[mi][ni][2];
            v1.y = alpha * acc[mi][ni][3];
            if (RES) {
                const float2 r0 = *(const float2*)(Res + row0 * ldc + col0);
                const float2 r1 = *(const float2*)(Res + (row0 + 8) * ldc + col0);
                v0.x += r0.x; v0.y += r0.y;
                v1.x += r1.x; v1.y += r1.y;
            }
            *(float2*)(C + row0 * ldc + col0) = v0;
            *(float2*)(C + (row0 + 8) * ldc + col0) = v1;
        }
    }
}

// =================================================================
// Scores kernel: attn_unnorm = exp(0.125 * Qh @ Kh^T), triple-tf32.
// BM=128, BN=64, BK=32, warps 4x2 of WM=32,WN=32. Writes per-row
// partial sums to g_part (deterministic, no atomics).
// =================================================================
__global__ __launch_bounds__(256, 2) void scores_kernel(
    const float* __restrict__ qp, const float* __restrict__ kp,
    float* __restrict__ attn, float* __restrict__ part)
{
    constexpr int BM = 128, BN = 64, BK = 32;
    constexpr int A_WORDS = BM * (BK + 4);
    constexpr int B_WORDS = BN * (BK + 4);
    constexpr int STAGE_WORDS = A_WORDS + B_WORDS;

    extern __shared__ float smemf[];
    __shared__ float rowpart[2][BM];

    const int z = blockIdx.z;
    const int b = z >> 4, h = z & 15;
    const float* A = qp + (long long)b * S_LEN * DMODEL + h * DHEAD;
    const float* B = kp + (long long)b * S_LEN * DMODEL + h * DHEAD;
    float* C = attn + (long long)z * S_LEN * S_LEN;

    const int tid  = threadIdx.x;
    const int warp = tid >> 5;
    const int lane = tid & 31;
    const int g = lane >> 2;
    const int t = lane & 3;
    const int wm0 = (warp >> 1) * 32;
    const int wn0 = (warp & 1) * 32;
    const int wc  = warp & 1;
    const int bm = blockIdx.y * BM, bn = blockIdx.x * BN;

    float acc[2][4][4];
#pragma unroll
    for (int i = 0; i < 2; i++)
#pragma unroll
        for (int j = 0; j < 4; j++)
#pragma unroll
            for (int r = 0; r < 4; r++) acc[i][j][r] = 0.0f;

    auto load_tile = [&](int it, int stage) {
        float* As = smemf + stage * STAGE_WORDS;
        float* Bs = As + A_WORDS;
        const int k0 = it * BK;
#pragma unroll
        for (int i = tid; i < BM * BK / 4; i += 256) {
            int r = i / 8, c = (i % 8) * 4;
            uint32_t dst = (uint32_t)__cvta_generic_to_shared(As + r * (BK + 4) + c);
            cp_async16(dst, A + (long long)(bm + r) * DMODEL + k0 + c);
        }
#pragma unroll
        for (int i = tid; i < BN * BK / 4; i += 256) {
            int r = i / 8, c = (i % 8) * 4;
            uint32_t dst = (uint32_t)__cvta_generic_to_shared(Bs + r * (BK + 4) + c);
            cp_async16(dst, B + (long long)(bn + r) * DMODEL + k0 + c);
        }
    };

    load_tile(0, 0);
    cp_commit();

#pragma unroll
    for (int it = 0; it < 2; it++) {       // K = 64 = 2 * BK
        if (it == 0) {
            load_tile(1, 1);
            cp_commit();
            cp_wait<1>();
        } else {
            cp_wait<0>();
        }
        __syncthreads();

        const float* As = smemf + it * STAGE_WORDS;
        const float* Bs = As + A_WORDS;

#pragma unroll
        for (int ks = 0; ks < BK / 8; ks++) {
            float afv[2][4], bfv[4][2];
#pragma unroll
            for (int mi = 0; mi < 2; mi++) {
                const int r0 = wm0 + mi * 16 + g;
                const int c0 = ks * 8 + t;
                afv[mi][0] = As[(r0    ) * (BK + 4) + c0    ];
                afv[mi][1] = As[(r0 + 8) * (BK + 4) + c0    ];
                afv[mi][2] = As[(r0    ) * (BK + 4) + c0 + 4];
                afv[mi][3] = As[(r0 + 8) * (BK + 4) + c0 + 4];
            }
#pragma unroll
            for (int ni = 0; ni < 4; ni++) {
                const int n0 = wn0 + ni * 8 + g;
                bfv[ni][0] = Bs[n0 * (BK + 4) + ks * 8 + t    ];
                bfv[ni][1] = Bs[n0 * (BK + 4) + ks * 8 + t + 4];
            }
            uint32_t ah[2][4], al[2][4], bh[4][2], bl[4][2];
#pragma unroll
            for (int mi = 0; mi < 2; mi++)
#pragma unroll
                for (int r = 0; r < 4; r++) {
                    ah[mi][r] = f2tf32(afv[mi][r]);
                    al[mi][r] = f2tf32(afv[mi][r] - __uint_as_float(ah[mi][r]));
                }
#pragma unroll
            for (int ni = 0; ni < 4; ni++)
#pragma unroll
                for (int r = 0; r < 2; r++) {
                    bh[ni][r] = f2tf32(bfv[ni][r]);
                    bl[ni][r] = f2tf32(bfv[ni][r] - __uint_as_float(bh[ni][r]));
                }
#pragma unroll
            for (int mi = 0; mi < 2; mi++)
#pragma unroll
                for (int ni = 0; ni < 4; ni++) {
                    mma_tf32(acc[mi][ni], al[mi], bh[ni]);
                    mma_tf32(acc[mi][ni], ah[mi], bl[ni]);
                    mma_tf32(acc[mi][ni], ah[mi], bh[ni]);
                }
        }
        __syncthreads();
    }

    // ---- epilogue: exp, store unnormalized, reduce row partials ----
    float rsum[2][2] = {{0.f, 0.f}, {0.f, 0.f}};
#pragma unroll
    for (int mi = 0; mi < 2; mi++) {
#pragma unroll
        for (int ni = 0; ni < 4; ni++) {
#pragma unroll
            for (int r = 0; r < 4; r++)
                acc[mi][ni][r] = __expf(0.125f * acc[mi][ni][r]);
            rsum[mi][0] += acc[mi][ni][0] + acc[mi][ni][1];
            rsum[mi][1] += acc[mi][ni][2] + acc[mi][ni][3];

            const long long row0 = bm + wm0 + mi * 16 + g;
            const long long col0 = bn + wn0 + ni * 8 + t * 2;
            float2 v0 = {acc[mi][ni][0], acc[mi][ni][1]};
            float2 v1 = {acc[mi][ni][2], acc[mi][ni][3]};
            *(float2*)(C + row0 * S_LEN + col0) = v0;
            *(float2*)(C + (row0 + 8) * S_LEN + col0) = v1;
        }
    }
#pragma unroll
    for (int mi = 0; mi < 2; mi++)
#pragma unroll
        for (int s = 0; s < 2; s++) {
            float v = rsum[mi][s];
            v += __shfl_xor_sync(0xffffffffu, v, 1);
            v += __shfl_xor_sync(0xffffffffu, v, 2);
            if (t == 0) rowpart[wc][wm0 + mi * 16 + s * 8 + g] = v;
        }
    __syncthreads();
    if (tid < BM) {
        float p = rowpart[0][tid] + rowpart[1][tid];
        part[((long long)z * S_LEN + bm + tid) * NCHUNK + blockIdx.x] = p;
    }
}

// =================================================================
// PV kernel: normalize attn in-place (write p = e/s) and compute
// out = (e @ V) * (1/s). BM=128, BN=64(=DHEAD), BK=32, single tf32.
// =================================================================
__global__ __launch_bounds__(256, 2) void pv_kernel(
    float* __restrict__ attn, const float* __restrict__ vp,
    float* __restrict__ ao, const float* __restrict__ part)
{
    constexpr int BM = 128, BN = 64, BK = 32;
    constexpr int A_WORDS = BM * (BK + 4);
    constexpr int B_WORDS = BK * (BN + 4);
    constexpr int STAGE_WORDS = A_WORDS + B_WORDS;

    extern __shared__ float smemf[];
    __shared__ float sInv[BM];

    const int z = blockIdx.z;
    const int b = z >> 4, h = z & 15;
    float* A = attn + (long long)z * S_LEN * S_LEN;
    const float* B = vp + (long long)b * S_LEN * DMODEL + h * DHEAD;
    float* C = ao + (long long)b * S_LEN * DMODEL + h * DHEAD;

    const int tid  = threadIdx.x;
    const int warp = tid >> 5;
    const int lane = tid & 31;
    const int g = lane >> 2;
    const int t = lane & 3;
    const int wm0 = (warp >> 1) * 32;
    const int wn0 = (warp & 1) * 32;
    const int bm = blockIdx.y * BM;

    // row inverse sums
    if (tid < BM) {
        const float* p = part + ((long long)z * S_LEN + bm + tid) * NCHUNK;
        float s = 0.0f;
#pragma unroll
        for (int j = 0; j < NCHUNK; j++) s += p[j];
        sInv[tid] = 1.0f / s;
    }

    float acc[2][4][4];
#pragma unroll
    for (int i = 0; i < 2; i++)
#pragma unroll
        for (int j = 0; j < 4; j++)
#pragma unroll
            for (int r = 0; r < 4; r++) acc[i][j][r] = 0.0f;

    auto load_tile = [&](int it, int stage) {
        float* As = smemf + stage * STAGE_WORDS;
        float* Bs = As + A_WORDS;
        const int k0 = it * BK;
#pragma unroll
        for (int i = tid; i < BM * BK / 4; i += 256) {
            int r = i / 8, c = (i % 8) * 4;
            uint32_t dst = (uint32_t)__cvta_generic_to_shared(As + r * (BK + 4) + c);
            cp_async16(dst, A + (long long)(bm + r) * S_LEN + k0 + c);
        }
#pragma unroll
        for (int i = tid; i < BK * BN / 4; i += 256) {
            int r = i / 16, c = (i % 16) * 4;
            uint32_t dst = (uint32_t)__cvta_generic_to_shared(Bs + r * (BN + 4) + c);
            cp_async16(dst, B + (long long)(k0 + r) * DMODEL + c);
        }
    };

    load_tile(0, 0);
    cp_commit();

    const int nIter = S_LEN / BK;   // 64
    for (int it = 0; it < nIter; it++) {
        if (it + 1 < nIter) {
            load_tile(it + 1, (it + 1) & 1);
            cp_commit();
            cp_wait<1>();
        } else {
            cp_wait<0>();
        }
        __syncthreads();

        const float* As = smemf + (it & 1) * STAGE_WORDS;
        const float* Bs = As + A_WORDS;

        // write normalized attn for this tile (data already in smem)
#pragma unroll
        for (int i = tid; i < BM * BK; i += 256) {
            const int r = i >> 5, c = i & 31;
            A[(long long)(bm + r) * S_LEN + it * BK + c] = As[r * (BK + 4) + c] * sInv[r];
        }

#pragma unroll
        for (int ks = 0; ks < BK / 8; ks++) {
            uint32_t ah[2][4], bh[4][2];
#pragma unroll
            for (int mi = 0; mi < 2; mi++) {
                const int r0 = wm0 + mi * 16 + g;
                const int c0 = ks * 8 + t;
                ah[mi][0] = f2tf32(As[(r0    ) * (BK + 4) + c0    ]);
                ah[mi][1] = f2tf32(As[(r0 + 8) * (BK + 4) + c0    ]);
                ah[mi][2] = f2tf32(As[(r0    ) * (BK + 4) + c0 + 4]);
                ah[mi][3] = f2tf32(As[(r0 + 8) * (BK + 4) + c0 + 4]);
            }
#pragma unroll
            for (int ni = 0; ni < 4; ni++) {
                const int n0 = wn0 + ni * 8 + g;
                bh[ni][0] = f2tf32(Bs[(ks * 8 + t    ) * (BN + 4) + n0]);
                bh[ni][1] = f2tf32(Bs[(ks * 8 + t + 4) * (BN + 4) + n0]);
            }
#pragma unroll
            for (int mi = 0; mi < 2; mi++)
#pragma unroll
                for (int ni = 0; ni < 4; ni++)
                    mma_tf32(acc[mi][ni], ah[mi], bh[ni]);
        }
        __syncthreads();
    }

    // epilogue: scale by 1/s and store
#pragma unroll
    for (int mi = 0; mi < 2; mi++) {
#pragma unroll
        for (int ni = 0; ni < 4; ni++) {
            const int rl0 = wm0 + mi * 16 + g;
            const long long row0 = bm + rl0;
            const long long col0 = wn0 + ni * 8 + t * 2;
            float2 v0, v1;
            v0.x = acc[mi][ni][0] * sInv[rl0];
            v0.y = acc[mi][ni][1] * sInv[rl0];
            v1.x = acc[mi][ni][2] * sInv[rl0 + 8];
            v1.y = acc[mi][ni][3] * sInv[rl0 + 8];
            *(float2*)(C + row0 * DMODEL + col0) = v0;
            *(float2*)(C + (row0 + 8) * DMODEL + col0) = v1;
        }
    }
}

// =================================================================
// In-place LayerNorm over rows of length DMODEL (1024). 256 threads.
// =================================================================
__global__ __launch_bounds__(256) void ln_kernel(float* __restrict__ x,
                                                 const float* __restrict__ gamma,
                                                 const float* __restrict__ beta)
{
    float* row = x + (size_t)blockIdx.x * DMODEL;
    const int tid = threadIdx.x;
    __shared__ float ssum[8], ssq[8];

    float v[4];
    float s = 0.0f, sq = 0.0f;
#pragma unroll
    for (int j = 0; j < 4; j++) {
        v[j] = row[tid + j * 256];
        s += v[j];
        sq += v[j] * v[j];
    }
#pragma unroll
    for (int o = 16; o > 0; o >>= 1) {
        s  += __shfl_xor_sync(0xffffffffu, s, o);
        sq += __shfl_xor_sync(0xffffffffu, sq, o);
    }
    if ((tid & 31) == 0) { ssum[tid >> 5] = s; ssq[tid >> 5] = sq; }
    __syncthreads();
    s = 0.0f; sq = 0.0f;
#pragma unroll
    for (int j = 0; j < 8; j++) { s += ssum[j]; sq += ssq[j]; }

    const float mu = s * (1.0f / DMODEL);
    const float var = sq * (1.0f / DMODEL) - mu * mu;
    const float rstd = rsqrtf(var + 1e-6f);
#pragma unroll
    for (int j = 0; j < 4; j++) {
        const int c = tid + j * 256;
        row[c] = (v[j] - mu) * rstd * gamma[c] + beta[c];
    }
}

// =================================================================
static constexpr int PROJ3_SMEM = 2 * (128 * 36 + 64 * 36) * 4;     // 55296 B (triple, BN=64)
static constexpr int BIG_SMEM   = 2 * (128 * 36 + 128 * 36) * 4;    // 73728 B (single, BN=128)
static constexpr int SC_SMEM    = 2 * (128 * 36 + 64 * 36) * 4;     // 55296 B
static constexpr int PV_SMEM    = 2 * (128 * 36 + 32 * 68) * 4;     // 54272 B

extern "C" void kernel_launch(void* const* d_in, const int* in_sizes, int n_in,
                              void* d_out, int out_size)
{
    const float* q     = (const float*)d_in[0];
    const float* k     = (const float*)d_in[1];
    const float* v     = (const float*)d_in[2];
    const float* w_q   = (const float*)d_in[3];
    const float* w_k   = (const float*)d_in[4];
    const float* w_v   = (const float*)d_in[5];
    const float* w_fc  = (const float*)d_in[6];
    const float* gamma = (const float*)d_in[7];
    const float* beta  = (const float*)d_in[8];

    float *qp, *kp, *vp, *ao, *part;
    cudaGetSymbolAddress((void**)&qp, g_qp);
    cudaGetSymbolAddress((void**)&kp, g_kp);
    cudaGetSymbolAddress((void**)&vp, g_vp);
    cudaGetSymbolAddress((void**)&ao, g_ao);
    cudaGetSymbolAddress((void**)&part, g_part);

    float* out  = (float*)d_out;
    float* attn = out + (size_t)MROWS * DMODEL;   // [B, H, Sq, Sk] fp32

    cudaFuncSetAttribute(gemm_tc<128,64,32,32,32,true,false,true,2>,
                         cudaFuncAttributeMaxDynamicSharedMemorySize, PROJ3_SMEM);
    cudaFuncSetAttribute(gemm_tc<128,128,32,32,64,true,false,false,1>,
                         cudaFuncAttributeMaxDynamicSharedMemorySize, BIG_SMEM);
    cudaFuncSetAttribute(gemm_tc<128,128,32,32,64,true,true,false,1>,
                         cudaFuncAttributeMaxDynamicSharedMemorySize, BIG_SMEM);
    cudaFuncSetAttribute(scores_kernel,
                         cudaFuncAttributeMaxDynamicSharedMemorySize, SC_SMEM);
    cudaFuncSetAttribute(pv_kernel,
                         cudaFuncAttributeMaxDynamicSharedMemorySize, PV_SMEM);

    dim3 blk(256);

    // --- Q/K projections (triple, BN=64 for 2 CTAs/SM) ---
    {
        dim3 g(DMODEL / 64, MROWS / 128, 1);
        gemm_tc<128,64,32,32,32,true,false,true,2><<<g, blk, PROJ3_SMEM>>>(
            q, DMODEL, w_q, DMODEL, qp, DMODEL, DMODEL, 1.0f, nullptr);
        gemm_tc<128,64,32,32,32,true,false,true,2><<<g, blk, PROJ3_SMEM>>>(
            k, DMODEL, w_k, DMODEL, kp, DMODEL, DMODEL, 1.0f, nullptr);
    }
    // --- V projection (single) ---
    {
        dim3 g(DMODEL / 128, MROWS / 128, 1);
        gemm_tc<128,128,32,32,64,true,false,false,1><<<g, blk, BIG_SMEM>>>(
            v, DMODEL, w_v, DMODEL, vp, DMODEL, DMODEL, 1.0f, nullptr);
    }

    // --- scores + exp + partial sums ---
    {
        dim3 g(S_LEN / 64, S_LEN / 128, NZ);
        scores_kernel<<<g, blk, SC_SMEM>>>(qp, kp, attn, part);
    }

    // --- PV + in-place softmax normalization of attn ---
    {
        dim3 g(1, S_LEN / 128, NZ);
        pv_kernel<<<g, blk, PV_SMEM>>>(attn, vp, ao, part);
    }

    // --- fc + residual ---
    {
        dim3 g(DMODEL / 128, MROWS / 128, 1);
        gemm_tc<128,128,32,32,64,true,true,false,1><<<g, blk, BIG_SMEM>>>(
            ao, DMODEL, w_fc, DMODEL, out, DMODEL, DMODEL, 1.0f, q);
    }

    // --- layernorm in place ---
    ln_kernel<<<MROWS, blk>>>(out, gamma, beta);
}